// round 3
// baseline (speedup 1.0000x reference)
#include <cuda_runtime.h>
#include <math.h>

#define NPIX       65536      // 64 * 32 * 32 pixels
#define KEMB       1024
#define DIM        256
#define HW         1024       // 32*32
#define OUT_ELEMS  16777216   // 64*256*32*32
#define ENC_ELEMS  67108864   // 65536*1024

// ---- device scratch (no allocations allowed) ----
__device__ int   g_idx[NPIX];
__device__ float g_xsq[NPIX];
__device__ float g_ensq[KEMB];
__device__ int   g_counts[KEMB];
__device__ float g_loss;

// ---- zero per-call state (graph replays!) ----
__global__ void vq_init() {
    int t = threadIdx.x;
    if (t < KEMB) g_counts[t] = 0;
    if (t == 0)   g_loss = 0.0f;
}

// ---- ||e||^2 per embedding row ----
__global__ void vq_ensq(const float* __restrict__ emb) {
    int warp = (blockIdx.x * blockDim.x + threadIdx.x) >> 5;
    int lane = threadIdx.x & 31;
    if (warp >= KEMB) return;
    const float* row = emb + (size_t)warp * DIM;
    float s = 0.f;
    #pragma unroll
    for (int j = 0; j < DIM / 32; j++) { float v = row[lane + 32 * j]; s += v * v; }
    #pragma unroll
    for (int o = 16; o; o >>= 1) s += __shfl_xor_sync(0xffffffffu, s, o);
    if (lane == 0) g_ensq[warp] = s;
}

// ---- ||x||^2 per pixel: one block per batch image, thread = hw ----
__global__ void vq_xsq(const float* __restrict__ inp) {
    int b  = blockIdx.x;
    int hw = threadIdx.x;              // 1024 threads
    const float* base = inp + (size_t)b * DIM * HW + hw;
    float s = 0.f;
    #pragma unroll 8
    for (int c = 0; c < DIM; c++) { float v = base[(size_t)c * HW]; s = fmaf(v, v, s); }
    g_xsq[b * HW + hw] = s;
}

// ---- main argmin: 128-pixel x 128-emb tiles, D chunked by 32, 8x8 per thread ----
__global__ __launch_bounds__(256, 2)
void vq_argmin(const float* __restrict__ inp, const float* __restrict__ emb) {
    __shared__ float As[128][33];   // [pixel][dim-chunk], +1 pad -> conflict-free
    __shared__ float Bs[128][33];   // [emb][dim-chunk]
    __shared__ float sbD[128];
    __shared__ int   sbI[128];

    int tid = threadIdx.x;
    int tx = tid & 15;      // embedding fragment lane (stride-16 interleave)
    int ty = tid >> 4;      // pixel fragment lane

    int p0  = blockIdx.x * 128;          // 128 contiguous pixels, within one batch image
    int b   = p0 >> 10;
    int hw0 = p0 & 1023;
    const float* inp_b = inp + (size_t)b * DIM * HW + hw0;

    if (tid < 128) { sbD[tid] = INFINITY; sbI[tid] = 0x7fffffff; }

    float xq[8];
    #pragma unroll
    for (int j = 0; j < 8; j++) xq[j] = g_xsq[p0 + ty + 16 * j];

    for (int n0 = 0; n0 < KEMB; n0 += 128) {
        float acc[8][8];
        #pragma unroll
        for (int j = 0; j < 8; j++)
            #pragma unroll
            for (int k = 0; k < 8; k++) acc[j][k] = 0.f;

        #pragma unroll 1
        for (int d0 = 0; d0 < DIM; d0 += 32) {
            __syncthreads();
            { // load A tile: 128 pixels x 32 dims (coalesced over hw)
                int m  = tid & 127;
                int dr = tid >> 7;           // 0..1
                #pragma unroll
                for (int dd = 0; dd < 32; dd += 2)
                    As[m][dd + dr] = inp_b[(size_t)(d0 + dd + dr) * HW + m];
            }
            { // load B tile: 128 embeddings x 32 dims (coalesced over dim)
                int d  = tid & 31;
                int nr = tid >> 5;           // 0..7
                #pragma unroll
                for (int nn = 0; nn < 128; nn += 8)
                    Bs[nn + nr][d] = emb[(size_t)(n0 + nn + nr) * DIM + d0 + d];
            }
            __syncthreads();
            #pragma unroll
            for (int d = 0; d < 32; d++) {
                float a[8], bb[8];
                #pragma unroll
                for (int j = 0; j < 8; j++) a[j]  = As[ty + 16 * j][d];
                #pragma unroll
                for (int k = 0; k < 8; k++) bb[k] = Bs[tx + 16 * k][d];
                #pragma unroll
                for (int j = 0; j < 8; j++)
                    #pragma unroll
                    for (int k = 0; k < 8; k++)
                        acc[j][k] += a[j] * bb[k];
            }
        }
        __syncthreads();   // done reading As/Bs -> reuse them for the reduction

        float en[8];
        #pragma unroll
        for (int k = 0; k < 8; k++) en[k] = g_ensq[n0 + tx + 16 * k];

        #pragma unroll
        for (int j = 0; j < 8; j++) {
            float best = INFINITY; int bidx = 0x7fffffff;
            #pragma unroll
            for (int k = 0; k < 8; k++) {
                int   n = n0 + tx + 16 * k;
                // match ref's fp32 rounding: fl(fl(||x||^2 + ||e||^2) - 2*x.e)
                float t   = xq[j] + en[k];
                float dct = t - 2.0f * acc[j][k];
                if (dct < best || (dct == best && n < bidx)) { best = dct; bidx = n; }
            }
            int pix = ty + 16 * j;
            As[pix][tx] = best;
            Bs[pix][tx] = __int_as_float(bidx);
        }
        __syncthreads();
        if (tid < 128) {
            float best = sbD[tid]; int bidx = sbI[tid];
            #pragma unroll
            for (int t = 0; t < 16; t++) {
                float dct = As[tid][t];
                int   n   = __float_as_int(Bs[tid][t]);
                if (dct < best || (dct == best && n < bidx)) { best = dct; bidx = n; }
            }
            sbD[tid] = best; sbI[tid] = bidx;
        }
        __syncthreads();
    }
    if (tid < 128) g_idx[p0 + tid] = sbI[tid];
}

// ---- histogram of chosen codes ----
__global__ void vq_counts() {
    int t = blockIdx.x * blockDim.x + threadIdx.x;
    if (t < NPIX) atomicAdd(&g_counts[g_idx[t]], 1);
}

// ---- out = emb[idx] in [B,C,H,W] layout (== STE forward value) + loss sum ----
// scalar 32-bit stores: out region (d_out+1) is only 4B-aligned
__global__ void vq_gather(const float* __restrict__ inp, const float* __restrict__ emb,
                          float* __restrict__ out) {
    int e = blockIdx.x * blockDim.x + threadIdx.x;          // < 16777216
    int bb = e >> 18;
    int c  = (e >> 10) & 255;
    int hw = e & 1023;
    int n  = (bb << 10) | hw;

    float x  = inp[e];
    int   id = g_idx[n];
    float o  = __ldg(&emb[(size_t)id * DIM + c]);
    out[e] = o;

    float d  = o - x;
    float ls = d * d;
    #pragma unroll
    for (int off = 16; off; off >>= 1) ls += __shfl_xor_sync(0xffffffffu, ls, off);
    if ((threadIdx.x & 31) == 0) atomicAdd(&g_loss, ls);
}

// ---- one-hot encodings: 268 MB streaming write (scalar stores, 4B-aligned region) ----
__global__ void vq_enc(float* __restrict__ enc) {
    int e = blockIdx.x * blockDim.x + threadIdx.x;          // < 67108864
    int n = e >> 10;
    int k = e & 1023;
    enc[e] = (g_idx[n] == k) ? 1.0f : 0.0f;
}

// ---- loss + perplexity scalars ----
__global__ void vq_finalize(float* __restrict__ d_out) {
    __shared__ float sm[32];
    int t = threadIdx.x;                                    // 1024 threads
    float p = (float)g_counts[t] * (1.0f / 65536.0f);
    float s = p * logf(p + 1e-10f);
    #pragma unroll
    for (int o = 16; o; o >>= 1) s += __shfl_xor_sync(0xffffffffu, s, o);
    if ((t & 31) == 0) sm[t >> 5] = s;
    __syncthreads();
    if (t < 32) {
        s = sm[t];
        #pragma unroll
        for (int o = 16; o; o >>= 1) s += __shfl_xor_sync(0xffffffffu, s, o);
        if (t == 0) {
            d_out[0]             = 1.25f * g_loss * (1.0f / 16777216.0f); // (1+0.25)*mse
            d_out[1 + OUT_ELEMS] = expf(-s);
        }
    }
}

extern "C" void kernel_launch(void* const* d_in, const int* in_sizes, int n_in,
                              void* d_out, int out_size) {
    const float* inp = (const float*)d_in[0];   // [64,256,32,32]
    const float* emb = (const float*)d_in[1];   // [1024,256]
    float* out = (float*)d_out;                 // [loss | out | perplexity | encodings]

    vq_init    <<<1, 1024>>>();
    vq_ensq    <<<128, 256>>>(emb);
    vq_xsq     <<<64, 1024>>>(inp);
    vq_argmin  <<<NPIX / 128, 256>>>(inp, emb);
    vq_counts  <<<NPIX / 256, 256>>>();
    vq_gather  <<<OUT_ELEMS / 256, 256>>>(inp, emb, out + 1);
    vq_enc     <<<ENC_ELEMS / 256, 256>>>(out + 2 + OUT_ELEMS);
    vq_finalize<<<1, 1024>>>(out);
}

// round 4
// speedup vs baseline: 2.1374x; 2.1374x over previous
#include <cuda_runtime.h>
#include <math.h>

#define NPIX       65536      // 64 * 32 * 32 pixels
#define KEMB       1024
#define DIM        256
#define HW         1024       // 32*32
#define OUT_ELEMS  16777216   // 64*256*32*32
#define ENC_ELEMS  67108864   // 65536*1024

// ---- device scratch (no allocations allowed) ----
__device__ int   g_idx[NPIX];
__device__ float g_xsq[NPIX];
__device__ float g_ensq[KEMB];
__device__ int   g_counts[KEMB];
__device__ float g_loss;

// ---- zero per-call state (graph replays!) ----
__global__ void vq_init() {
    int t = threadIdx.x;
    if (t < KEMB) g_counts[t] = 0;
    if (t == 0)   g_loss = 0.0f;
}

// ---- ||e||^2 per embedding row ----
__global__ void vq_ensq(const float* __restrict__ emb) {
    int warp = (blockIdx.x * blockDim.x + threadIdx.x) >> 5;
    int lane = threadIdx.x & 31;
    if (warp >= KEMB) return;
    const float* row = emb + (size_t)warp * DIM;
    float s = 0.f;
    #pragma unroll
    for (int j = 0; j < DIM / 32; j++) { float v = row[lane + 32 * j]; s += v * v; }
    #pragma unroll
    for (int o = 16; o; o >>= 1) s += __shfl_xor_sync(0xffffffffu, s, o);
    if (lane == 0) g_ensq[warp] = s;
}

// ---- ||x||^2 per pixel ----
__global__ void vq_xsq(const float* __restrict__ inp) {
    int b  = blockIdx.x;
    int hw = threadIdx.x;              // 1024 threads
    const float* base = inp + (size_t)b * DIM * HW + hw;
    float s = 0.f;
    #pragma unroll 8
    for (int c = 0; c < DIM; c++) { float v = base[(size_t)c * HW]; s = fmaf(v, v, s); }
    g_xsq[b * HW + hw] = s;
}

// ---- main argmin: 128-pixel x 128-emb tiles, packed-f32x2 FMA ----
// per-thread: 8 pixels (4 adjacent pairs: p = 2*ty + 32*jp + h) x 8 embeddings (n = tx + 16*k)
__global__ __launch_bounds__(256, 2)
void vq_argmin(const float* __restrict__ inp, const float* __restrict__ emb) {
    __shared__ float As[32][128];   // [d][pixel] transposed -> LDS.64 pixel pairs
    __shared__ float Bs[128][33];   // [emb][d], +1 pad -> conflict-free b reads
    __shared__ float sbD[128];
    __shared__ int   sbI[128];

    int tid = threadIdx.x;
    int tx = tid & 15;
    int ty = tid >> 4;

    int p0  = blockIdx.x * 128;
    int b   = p0 >> 10;
    int hw0 = p0 & 1023;
    const float* inp_b = inp + (size_t)b * (DIM * HW) + hw0;

    if (tid < 128) { sbD[tid] = INFINITY; sbI[tid] = 0x7fffffff; }

    float xq[4][2];
    #pragma unroll
    for (int jp = 0; jp < 4; jp++) {
        float2 v = *(const float2*)&g_xsq[p0 + 2 * ty + 32 * jp];
        xq[jp][0] = v.x; xq[jp][1] = v.y;
    }

    for (int n0 = 0; n0 < KEMB; n0 += 128) {
        unsigned long long acc[4][8];
        #pragma unroll
        for (int jp = 0; jp < 4; jp++)
            #pragma unroll
            for (int k = 0; k < 8; k++) acc[jp][k] = 0ULL;

        #pragma unroll 1
        for (int d0 = 0; d0 < DIM; d0 += 32) {
            __syncthreads();
            { // A tile: 32 d x 128 pixels, float4 LDG + STS.128, transposed layout
                int m4 = (tid & 31) * 4;
                int dl = tid >> 5;                  // 0..7
                #pragma unroll
                for (int pass = 0; pass < 4; pass++) {
                    int d = dl + 8 * pass;
                    float4 v = *(const float4*)&inp_b[(size_t)(d0 + d) * HW + m4];
                    *(float4*)&As[d][m4] = v;
                }
            }
            { // B tile: 128 emb x 32 d, float4 LDG + scalar STS (pad-33 rows)
                #pragma unroll
                for (int pass = 0; pass < 4; pass++) {
                    int fid = pass * 256 + tid;
                    int n   = fid >> 3;
                    int d4  = (fid & 7) * 4;
                    float4 v = *(const float4*)&emb[(size_t)(n0 + n) * DIM + d0 + d4];
                    Bs[n][d4 + 0] = v.x; Bs[n][d4 + 1] = v.y;
                    Bs[n][d4 + 2] = v.z; Bs[n][d4 + 3] = v.w;
                }
            }
            __syncthreads();
            #pragma unroll
            for (int d = 0; d < 32; d++) {
                const unsigned long long* arow = (const unsigned long long*)&As[d][0];
                unsigned long long a2[4];
                #pragma unroll
                for (int jp = 0; jp < 4; jp++) a2[jp] = arow[ty + 16 * jp];
                #pragma unroll
                for (int k = 0; k < 8; k++) {
                    unsigned int bv = __float_as_uint(Bs[tx + 16 * k][d]);
                    unsigned long long b2;
                    asm("mov.b64 %0, {%1, %1};" : "=l"(b2) : "r"(bv));
                    #pragma unroll
                    for (int jp = 0; jp < 4; jp++)
                        asm("fma.rn.f32x2 %0, %1, %2, %0;"
                            : "+l"(acc[jp][k]) : "l"(a2[jp]), "l"(b2));
                }
            }
        }
        __syncthreads();   // compute done -> safe to overlay reduction into As/Bs

        float en[8];
        #pragma unroll
        for (int k = 0; k < 8; k++) en[k] = g_ensq[n0 + tx + 16 * k];

        float* redD = &As[0][0];       // 128*17 <= 4096 floats
        int*   redI = (int*)&Bs[0][0]; // 128*17 <= 4224 floats

        #pragma unroll
        for (int jp = 0; jp < 4; jp++) {
            #pragma unroll
            for (int h = 0; h < 2; h++) {
                float best = INFINITY; int bidx = 0x7fffffff;
                #pragma unroll
                for (int k = 0; k < 8; k++) {
                    float lo, hi;
                    asm("mov.b64 {%0, %1}, %2;" : "=f"(lo), "=f"(hi) : "l"(acc[jp][k]));
                    float dot = h ? hi : lo;
                    // match ref's fp32 rounding: fl(fl(||x||^2 + ||e||^2) - 2*x.e)
                    float t2  = xq[jp][h] + en[k];
                    float dct = t2 - 2.0f * dot;
                    int   n   = n0 + tx + 16 * k;
                    if (dct < best || (dct == best && n < bidx)) { best = dct; bidx = n; }
                }
                int p = 2 * ty + 32 * jp + h;
                redD[p * 17 + tx] = best;
                redI[p * 17 + tx] = bidx;
            }
        }
        __syncthreads();
        if (tid < 128) {
            float best = sbD[tid]; int bidx = sbI[tid];
            #pragma unroll
            for (int t = 0; t < 16; t++) {
                float dct = redD[tid * 17 + t];
                int   n   = redI[tid * 17 + t];
                if (dct < best || (dct == best && n < bidx)) { best = dct; bidx = n; }
            }
            sbD[tid] = best; sbI[tid] = bidx;
        }
        __syncthreads();
    }
    if (tid < 128) g_idx[p0 + tid] = sbI[tid];
}

// ---- histogram of chosen codes ----
__global__ void vq_counts() {
    int t = blockIdx.x * blockDim.x + threadIdx.x;
    if (t < NPIX) atomicAdd(&g_counts[g_idx[t]], 1);
}

// ---- gather: block = 32 pixels x 256 channels; coalesced emb reads, smem
// transpose, coalesced [B,C,H,W] writes; loss: one atomic per block ----
__global__ __launch_bounds__(256)
void vq_gather(const float* __restrict__ inp, const float* __restrict__ emb,
               float* __restrict__ out) {
    __shared__ float sm[256][33];   // [c][p]
    __shared__ int   sidx[32];
    __shared__ float sred[8];

    int tid = threadIdx.x;
    int blk = blockIdx.x;           // 2048
    int b   = blk >> 5;
    int hw0 = (blk & 31) * 32;
    int n0  = b * HW + hw0;

    if (tid < 32) sidx[tid] = g_idx[n0 + tid];
    __syncthreads();

    // read emb rows coalesced (float4), transpose into smem
    #pragma unroll
    for (int it = 0; it < 8; it++) {
        int p = it * 4 + (tid >> 6);
        int c = (tid & 63) * 4;
        float4 v = *(const float4*)&emb[(size_t)sidx[p] * DIM + c];
        sm[c + 0][p] = v.x; sm[c + 1][p] = v.y;
        sm[c + 2][p] = v.z; sm[c + 3][p] = v.w;
    }
    __syncthreads();

    // write out coalesced over hw; accumulate loss
    int p  = tid & 31;
    int c0 = (tid >> 5) * 32;       // 8 channel groups of 32
    const float* inp_base = inp + (size_t)b * (DIM * HW) + hw0 + p;
    float*       out_base = out + (size_t)b * (DIM * HW) + hw0 + p;
    float ls = 0.f;
    #pragma unroll
    for (int i = 0; i < 32; i++) {
        int c = c0 + i;
        float o = sm[c][p];
        float x = inp_base[(size_t)c * HW];
        out_base[(size_t)c * HW] = o;
        float d = o - x;
        ls = fmaf(d, d, ls);
    }
    #pragma unroll
    for (int o = 16; o; o >>= 1) ls += __shfl_xor_sync(0xffffffffu, ls, o);
    if ((tid & 31) == 0) sred[tid >> 5] = ls;
    __syncthreads();
    if (tid == 0) {
        float s = 0.f;
        #pragma unroll
        for (int w = 0; w < 8; w++) s += sred[w];
        atomicAdd(&g_loss, s);
    }
}

// ---- one-hot encodings: 268 MB streaming float2 writes (region is 8B-aligned) ----
__global__ void vq_enc(float2* __restrict__ enc) {
    int t  = blockIdx.x * blockDim.x + threadIdx.x;   // < 33554432
    int n  = t >> 9;
    int k2 = (t & 511) << 1;
    int id = g_idx[n];
    float2 v;
    v.x = (id == k2)     ? 1.0f : 0.0f;
    v.y = (id == k2 + 1) ? 1.0f : 0.0f;
    enc[t] = v;
}

// ---- loss + perplexity scalars ----
__global__ void vq_finalize(float* __restrict__ d_out) {
    __shared__ float sm[32];
    int t = threadIdx.x;                                    // 1024 threads
    float p = (float)g_counts[t] * (1.0f / 65536.0f);
    float s = p * logf(p + 1e-10f);
    #pragma unroll
    for (int o = 16; o; o >>= 1) s += __shfl_xor_sync(0xffffffffu, s, o);
    if ((t & 31) == 0) sm[t >> 5] = s;
    __syncthreads();
    if (t < 32) {
        s = sm[t];
        #pragma unroll
        for (int o = 16; o; o >>= 1) s += __shfl_xor_sync(0xffffffffu, s, o);
        if (t == 0) {
            d_out[0]             = 1.25f * g_loss * (1.0f / 16777216.0f); // (1+0.25)*mse
            d_out[1 + OUT_ELEMS] = expf(-s);
        }
    }
}

extern "C" void kernel_launch(void* const* d_in, const int* in_sizes, int n_in,
                              void* d_out, int out_size) {
    const float* inp = (const float*)d_in[0];   // [64,256,32,32]
    const float* emb = (const float*)d_in[1];   // [1024,256]
    float* out = (float*)d_out;                 // [loss | out | perplexity | encodings]

    vq_init    <<<1, 1024>>>();
    vq_ensq    <<<128, 256>>>(emb);
    vq_xsq     <<<64, 1024>>>(inp);
    vq_argmin  <<<NPIX / 128, 256>>>(inp, emb);
    vq_counts  <<<NPIX / 256, 256>>>();
    vq_gather  <<<2048, 256>>>(inp, emb, out + 1);
    vq_enc     <<<ENC_ELEMS / 2 / 256, 256>>>((float2*)(out + 2 + OUT_ELEMS));
    vq_finalize<<<1, 1024>>>(out);
}

// round 9
// speedup vs baseline: 2.9914x; 1.3995x over previous
#include <cuda_runtime.h>
#include <cuda_bf16.h>
#include <cuda_fp16.h>
#include <math.h>
#include <stdint.h>

#define NPIX       65536      // 64 * 32 * 32 pixels
#define KEMB       1024
#define DIM        256
#define HW         1024       // 32*32
#define OUT_ELEMS  16777216   // 64*256*32*32
#define ENC_ELEMS  67108864   // 65536*1024

// ---- device scratch (no allocations allowed) ----
__device__ int   g_idx[NPIX];
__device__ float g_xsq[NPIX];
__device__ float g_ensq[KEMB];
__device__ int   g_counts[KEMB];
__device__ float g_loss;
__device__ __nv_bfloat16 g_a0[NPIX * DIM];   // bf16(x), transposed [pix][dim]
__device__ __nv_bfloat16 g_e0[KEMB * DIM];   // bf16(e), [emb][dim]
__device__ float         g_xt[NPIX * DIM];   // fp32 x, transposed [pix][dim]
__device__ __half        g_dots[(size_t)NPIX * KEMB]; // approx dots, f16

// ================= PTX helpers (portable: sm_75+/sm_80+) =================
__device__ __forceinline__ uint32_t smem_to_u32(const void* p) {
    uint32_t a;
    asm("{ .reg .u64 t; cvta.to.shared.u64 t, %1; cvt.u32.u64 %0, t; }" : "=r"(a) : "l"(p));
    return a;
}
__device__ __forceinline__ void ldsm_x4(uint32_t& r0, uint32_t& r1, uint32_t& r2,
                                        uint32_t& r3, uint32_t addr) {
    asm volatile("ldmatrix.sync.aligned.m8n8.x4.shared.b16 {%0,%1,%2,%3}, [%4];"
        : "=r"(r0), "=r"(r1), "=r"(r2), "=r"(r3) : "r"(addr));
}
__device__ __forceinline__ void mma_bf16(float* c, const uint32_t* a,
                                         uint32_t b0, uint32_t b1) {
    asm volatile("mma.sync.aligned.m16n8k16.row.col.f32.bf16.bf16.f32 "
        "{%0,%1,%2,%3}, {%4,%5,%6,%7}, {%8,%9}, {%0,%1,%2,%3};"
        : "+f"(c[0]), "+f"(c[1]), "+f"(c[2]), "+f"(c[3])
        : "r"(a[0]), "r"(a[1]), "r"(a[2]), "r"(a[3]), "r"(b0), "r"(b1));
}

// ================= small helper kernels =================
__global__ void vq_init() {
    int t = threadIdx.x;
    if (t < KEMB) g_counts[t] = 0;
    if (t == 0)   g_loss = 0.0f;
}

__global__ void vq_ensq(const float* __restrict__ emb) {
    int warp = (blockIdx.x * blockDim.x + threadIdx.x) >> 5;
    int lane = threadIdx.x & 31;
    if (warp >= KEMB) return;
    const float* row = emb + (size_t)warp * DIM;
    float s = 0.f;
    #pragma unroll
    for (int j = 0; j < DIM / 32; j++) { float v = row[lane + 32 * j]; s += v * v; }
    #pragma unroll
    for (int o = 16; o; o >>= 1) s += __shfl_xor_sync(0xffffffffu, s, o);
    if (lane == 0) g_ensq[warp] = s;
}

// identical numerics to the passing rounds-3/4 version
__global__ void vq_xsq(const float* __restrict__ inp) {
    int b  = blockIdx.x;
    int hw = threadIdx.x;
    const float* base = inp + (size_t)b * DIM * HW + hw;
    float s = 0.f;
    #pragma unroll 8
    for (int c = 0; c < DIM; c++) { float v = base[(size_t)c * HW]; s = fmaf(v, v, s); }
    g_xsq[b * HW + hw] = s;
}

// ---- bf16 copy of emb (already [n][k]) ----
__global__ void vq_prep_emb(const float* __restrict__ emb) {
    int e = blockIdx.x * 256 + threadIdx.x;   // grid 1024 -> 262144
    g_e0[e] = __float2bfloat16(emb[e]);
}

// ---- transpose inp: [b][c][hw] -> [pix][c]; write fp32 copy + bf16 copy ----
__global__ __launch_bounds__(256)
void vq_prep_a(const float* __restrict__ inp) {
    __shared__ float sm[256][35];
    int b = blockIdx.x >> 5, hw0 = (blockIdx.x & 31) * 32;
    const float* src = inp + (size_t)b * (DIM * HW) + hw0;
    int tid = threadIdx.x;
    #pragma unroll
    for (int pass = 0; pass < 8; pass++) {
        int idx = pass * 256 + tid;          // 0..2047
        int c = idx >> 3, h4 = (idx & 7) * 4;
        float4 v = *(const float4*)&src[(size_t)c * HW + h4];
        sm[c][h4] = v.x; sm[c][h4 + 1] = v.y; sm[c][h4 + 2] = v.z; sm[c][h4 + 3] = v.w;
    }
    __syncthreads();
    int p0 = b * HW + hw0;
    #pragma unroll
    for (int pass = 0; pass < 8; pass++) {
        int idx = pass * 256 + tid;
        int hw = idx >> 6, c4 = (idx & 63) * 4;
        float v0 = sm[c4][hw], v1 = sm[c4 + 1][hw], v2 = sm[c4 + 2][hw], v3 = sm[c4 + 3][hw];
        size_t o = (size_t)(p0 + hw) * DIM + c4;
        *(float4*)&g_xt[o] = make_float4(v0, v1, v2, v3);
        uint32_t lo = (uint32_t)__bfloat16_as_ushort(__float2bfloat16(v0)) |
                      ((uint32_t)__bfloat16_as_ushort(__float2bfloat16(v1)) << 16);
        uint32_t hi = (uint32_t)__bfloat16_as_ushort(__float2bfloat16(v2)) |
                      ((uint32_t)__bfloat16_as_ushort(__float2bfloat16(v3)) << 16);
        *(uint2*)&g_a0[o] = make_uint2(lo, hi);
    }
}

// ================= phase 1: bf16 HMMA GEMM -> f16 dots =================
// CTA = 128 pixels x all 1024 codes. 8 warps, warp = 16 pixel rows.
// smem: A tile 128x256 bf16 (stride 528B), B tile 128x256 bf16 (stride 528B).
#define SM_STRIDE 528
#define SM_B_OFF  67584
#define GEMM_SMEM (2 * 67584)

__global__ __launch_bounds__(256, 1)
void vq_gemm() {
    extern __shared__ char sm[];
    uint32_t smA = smem_to_u32(sm);
    uint32_t smB = smA + SM_B_OFF;
    int tid = threadIdx.x, w = tid >> 5, lane = tid & 31;
    int p0 = blockIdx.x * 128;

    // fill A tile once
    for (int i = tid; i < 4096; i += 256) {
        int row = i >> 5, q = (i & 31) * 16;
        uint4 v = *(const uint4*)((const char*)g_a0 + (size_t)(p0 + row) * 512 + q);
        *(uint4*)(sm + row * SM_STRIDE + q) = v;
    }
    __syncthreads();

    // A fragments for all 16 k-steps (64 regs)
    uint32_t Af[16][4];
    {
        int lr = lane & 15, lc = lane >> 4;
        uint32_t abase = smA + (w * 16 + lr) * SM_STRIDE + lc * 16;
        #pragma unroll
        for (int s = 0; s < 16; s++)
            ldsm_x4(Af[s][0], Af[s][1], Af[s][2], Af[s][3], abase + s * 32);
    }

    int gb = lane >> 3, rl = lane & 7;
    for (int nt = 0; nt < 8; nt++) {
        __syncthreads();   // all warps done with previous B fragments
        for (int i = tid; i < 4096; i += 256) {
            int row = i >> 5, q = (i & 31) * 16;
            uint4 v = *(const uint4*)((const char*)g_e0 + (size_t)(nt * 128 + row) * 512 + q);
            *(uint4*)(sm + SM_B_OFF + row * SM_STRIDE + q) = v;
        }
        __syncthreads();

        float acc[16][4];
        #pragma unroll
        for (int t = 0; t < 16; t++)
            #pragma unroll
            for (int r = 0; r < 4; r++) acc[t][r] = 0.f;

        #pragma unroll
        for (int s2 = 0; s2 < 8; s2++) {
            #pragma unroll
            for (int t = 0; t < 16; t++) {
                uint32_t b0, b1, b2, b3;
                uint32_t baddr = smB + (t * 8 + rl) * SM_STRIDE + s2 * 64 + gb * 16;
                ldsm_x4(b0, b1, b2, b3, baddr);
                mma_bf16(acc[t], Af[2 * s2],     b0, b1);
                mma_bf16(acc[t], Af[2 * s2 + 1], b2, b3);
            }
        }

        // store f16 dots
        int r0 = p0 + w * 16 + (lane >> 2);
        int cb = nt * 128 + 2 * (lane & 3);
        #pragma unroll
        for (int t = 0; t < 16; t++) {
            __half2 lo = __floats2half2_rn(acc[t][0], acc[t][1]);
            __half2 hi = __floats2half2_rn(acc[t][2], acc[t][3]);
            *(__half2*)&g_dots[(size_t)r0 * KEMB + cb + t * 8]       = lo;
            *(__half2*)&g_dots[(size_t)(r0 + 8) * KEMB + cb + t * 8] = hi;
        }
    }
}

// ================= phase 2: candidate refine (exact fp32, ref rounding) ====
__global__ __launch_bounds__(256)
void vq_refine(const float* __restrict__ emb) {
    __shared__ float s_ensq[KEMB];
    __shared__ float s_x[8][256];
    __shared__ int   s_list[8][64];
    __shared__ int   s_cnt[8];

    int tid = threadIdx.x, w = tid >> 5, lane = tid & 31;
    for (int i = tid; i < KEMB; i += 256) s_ensq[i] = g_ensq[i];
    if (lane == 0) s_cnt[w] = 0;
    __syncthreads();

    int pix = blockIdx.x * 8 + w;
    float xq = g_xsq[pix];

    // stage fp32 x row
    for (int i = lane; i < 256; i += 32) s_x[w][i] = g_xt[(size_t)pix * DIM + i];

    // load this lane's 32 approx dots (f16)
    uint4 q[4];
    const uint4* dp = (const uint4*)(g_dots + (size_t)pix * KEMB) + lane * 4;
    #pragma unroll
    for (int i = 0; i < 4; i++) q[i] = dp[i];
    uint32_t dv[16];
    #pragma unroll
    for (int i = 0; i < 4; i++) {
        dv[4 * i] = q[i].x; dv[4 * i + 1] = q[i].y; dv[4 * i + 2] = q[i].z; dv[4 * i + 3] = q[i].w;
    }

    int cbase = lane * 32;
    float dap[32];
    float dmin = INFINITY;
    #pragma unroll
    for (int r = 0; r < 16; r++) {
        float2 f = __half22float2(*(__half2*)&dv[r]);
        float d0 = (xq + s_ensq[cbase + 2 * r])     - 2.0f * f.x;
        float d1 = (xq + s_ensq[cbase + 2 * r + 1]) - 2.0f * f.y;
        dap[2 * r] = d0; dap[2 * r + 1] = d1;
        dmin = fminf(dmin, fminf(d0, d1));
    }
    #pragma unroll
    for (int o = 16; o; o >>= 1) dmin = fminf(dmin, __shfl_xor_sync(0xffffffffu, dmin, o));

    // provable pruning threshold:
    //  |d_approx - d_ref| <= 2*(2^-8 * ||x|| * 0.015625 + 2.5e-4 f16 + slack)
    float thr = dmin + 2.44140625e-4f * sqrtf(xq) + 1.2e-3f;

    #pragma unroll
    for (int r = 0; r < 32; r++) {
        if (dap[r] <= thr) {
            int slot = atomicAdd(&s_cnt[w], 1);
            if (slot < 64) s_list[w][slot] = cbase + r;
        }
    }
    __syncwarp();
    int cnt = s_cnt[w];
    int ovf = (cnt > 64);
    int total = ovf ? KEMB : cnt;

    float bd = INFINITY; int bi = 0x7fffffff;
    for (int base = 0; base < total; base += 32) {
        int ci = base + lane;
        if (ci < total) {
            int cand = ovf ? ci : s_list[w][ci];
            const float* er = emb + (size_t)cand * DIM;
            float acc = 0.f;
            #pragma unroll 8
            for (int k = 0; k < 256; k++) acc = fmaf(s_x[w][k], er[k], acc);
            // ref rounding: fl(fl(||x||^2 + ||e||^2) - 2*x.e)
            float t2  = xq + s_ensq[cand];
            float dct = t2 - 2.0f * acc;
            if (dct < bd || (dct == bd && cand < bi)) { bd = dct; bi = cand; }
        }
    }
    #pragma unroll
    for (int o = 16; o; o >>= 1) {
        float od = __shfl_xor_sync(0xffffffffu, bd, o);
        int   oi = __shfl_xor_sync(0xffffffffu, bi, o);
        if (od < bd || (od == bd && oi < bi)) { bd = od; bi = oi; }
    }
    if (lane == 0) g_idx[pix] = bi;
}

// ================= downstream (unchanged) =================
__global__ void vq_counts() {
    int t = blockIdx.x * blockDim.x + threadIdx.x;
    if (t < NPIX) atomicAdd(&g_counts[g_idx[t]], 1);
}

__global__ __launch_bounds__(256)
void vq_gather(const float* __restrict__ inp, const float* __restrict__ emb,
               float* __restrict__ out) {
    __shared__ float sm[256][33];
    __shared__ int   sidx[32];
    __shared__ float sred[8];

    int tid = threadIdx.x;
    int blk = blockIdx.x;
    int b   = blk >> 5;
    int hw0 = (blk & 31) * 32;
    int n0  = b * HW + hw0;

    if (tid < 32) sidx[tid] = g_idx[n0 + tid];
    __syncthreads();

    #pragma unroll
    for (int it = 0; it < 8; it++) {
        int p = it * 4 + (tid >> 6);
        int c = (tid & 63) * 4;
        float4 v = *(const float4*)&emb[(size_t)sidx[p] * DIM + c];
        sm[c + 0][p] = v.x; sm[c + 1][p] = v.y;
        sm[c + 2][p] = v.z; sm[c + 3][p] = v.w;
    }
    __syncthreads();

    int p  = tid & 31;
    int c0 = (tid >> 5) * 32;
    const float* inp_base = inp + (size_t)b * (DIM * HW) + hw0 + p;
    float*       out_base = out + (size_t)b * (DIM * HW) + hw0 + p;
    float ls = 0.f;
    #pragma unroll
    for (int i = 0; i < 32; i++) {
        int c = c0 + i;
        float o = sm[c][p];
        float x = inp_base[(size_t)c * HW];
        out_base[(size_t)c * HW] = o;
        float d = o - x;
        ls = fmaf(d, d, ls);
    }
    #pragma unroll
    for (int o = 16; o; o >>= 1) ls += __shfl_xor_sync(0xffffffffu, ls, o);
    if ((tid & 31) == 0) sred[tid >> 5] = ls;
    __syncthreads();
    if (tid == 0) {
        float s = 0.f;
        #pragma unroll
        for (int w2 = 0; w2 < 8; w2++) s += sred[w2];
        atomicAdd(&g_loss, s);
    }
}

__global__ void vq_enc(float2* __restrict__ enc) {
    int t  = blockIdx.x * blockDim.x + threadIdx.x;   // < 33554432
    int n  = t >> 9;
    int k2 = (t & 511) << 1;
    int id = g_idx[n];
    float2 v;
    v.x = (id == k2)     ? 1.0f : 0.0f;
    v.y = (id == k2 + 1) ? 1.0f : 0.0f;
    enc[t] = v;
}

__global__ void vq_finalize(float* __restrict__ d_out) {
    __shared__ float sm[32];
    int t = threadIdx.x;
    float p = (float)g_counts[t] * (1.0f / 65536.0f);
    float s = p * logf(p + 1e-10f);
    #pragma unroll
    for (int o = 16; o; o >>= 1) s += __shfl_xor_sync(0xffffffffu, s, o);
    if ((t & 31) == 0) sm[t >> 5] = s;
    __syncthreads();
    if (t < 32) {
        s = sm[t];
        #pragma unroll
        for (int o = 16; o; o >>= 1) s += __shfl_xor_sync(0xffffffffu, s, o);
        if (t == 0) {
            d_out[0]             = 1.25f * g_loss * (1.0f / 16777216.0f);
            d_out[1 + OUT_ELEMS] = expf(-s);
        }
    }
}

extern "C" void kernel_launch(void* const* d_in, const int* in_sizes, int n_in,
                              void* d_out, int out_size) {
    const float* inp = (const float*)d_in[0];   // [64,256,32,32]
    const float* emb = (const float*)d_in[1];   // [1024,256]
    float* out = (float*)d_out;                 // [loss | out | perplexity | encodings]

    cudaFuncSetAttribute(vq_gemm, cudaFuncAttributeMaxDynamicSharedMemorySize, GEMM_SMEM);

    vq_init    <<<1, 1024>>>();
    vq_ensq    <<<128, 256>>>(emb);
    vq_xsq     <<<64, 1024>>>(inp);
    vq_prep_emb<<<1024, 256>>>(emb);
    vq_prep_a  <<<2048, 256>>>(inp);
    vq_gemm    <<<NPIX / 128, 256, GEMM_SMEM>>>();
    vq_refine  <<<NPIX / 8, 256>>>(emb);
    vq_counts  <<<NPIX / 256, 256>>>();
    vq_gather  <<<2048, 256>>>(inp, emb, out + 1);
    vq_enc     <<<ENC_ELEMS / 2 / 256, 256>>>((float2*)(out + 2 + OUT_ELEMS));
    vq_finalize<<<1, 1024>>>(out);
}